// round 7
// baseline (speedup 1.0000x reference)
#include <cuda_runtime.h>
#include <cuda_bf16.h>
#include <math.h>
#include <math_constants.h>
#include <cstdint>

#define CB 4
#define CN 1024
#define CD 1024
#define CH 8
#define CHD 128
#define CD4 4096

typedef __nv_bfloat16 bf16;

// ---------------------------------------------------------------------------
// Device-global scratch (fp32 dataflow, proven in R5)
// ---------------------------------------------------------------------------
__device__ __align__(1024) float g_normed[CB * CN * CD];              // 16 MB
__device__ __align__(1024) float g_normed2[CB * CN * CD];             // 16 MB
__device__ __align__(1024) float g_x1[CB * CN * CD];                  // 16 MB
__device__ __align__(1024) float g_scores[(size_t)32 * CN * CN];      // 128 MB
__device__ __align__(1024) float g_hbuf[(size_t)CB * CN * CD4];       // 64 MB

// ---------------------------------------------------------------------------
// Helpers
// ---------------------------------------------------------------------------
__device__ __forceinline__ void mma16816(float* d, const uint32_t* a,
                                         const uint32_t* b) {
    asm volatile(
        "mma.sync.aligned.m16n8k16.row.col.f32.bf16.bf16.f32 "
        "{%0,%1,%2,%3}, {%4,%5,%6,%7}, {%8,%9}, {%0,%1,%2,%3};"
        : "+f"(d[0]), "+f"(d[1]), "+f"(d[2]), "+f"(d[3])
        : "r"(a[0]), "r"(a[1]), "r"(a[2]), "r"(a[3]), "r"(b[0]), "r"(b[1]));
}

__device__ __forceinline__ void cp16(uint32_t dst, const void* src) {
    asm volatile("cp.async.cg.shared.global [%0], [%1], 16;"
                 :: "r"(dst), "l"(__cvta_generic_to_global(src)));
}
__device__ __forceinline__ void cp_commit() {
    asm volatile("cp.async.commit_group;" ::: "memory");
}
template <int N>
__device__ __forceinline__ void cp_wait() {
    asm volatile("cp.async.wait_group %0;" :: "n"(N) : "memory");
}
__device__ __forceinline__ uint32_t smem_u32(const void* p) {
    uint32_t a;
    asm("{ .reg .u64 t; cvta.to.shared.u64 t, %1; cvt.u32.u64 %0, t; }"
        : "=r"(a) : "l"(p));
    return a;
}

__device__ __forceinline__ uint32_t pack2(bf16 a, bf16 b) {
    __nv_bfloat162 p = __halves2bfloat162(a, b);
    return *reinterpret_cast<uint32_t*>(&p);
}
__device__ __forceinline__ void split4(float4 v, uint2& hi, uint2& lo) {
    bf16 h0 = __float2bfloat16_rn(v.x), h1 = __float2bfloat16_rn(v.y);
    bf16 h2 = __float2bfloat16_rn(v.z), h3 = __float2bfloat16_rn(v.w);
    hi.x = pack2(h0, h1);
    hi.y = pack2(h2, h3);
    lo.x = pack2(__float2bfloat16_rn(v.x - __bfloat162float(h0)),
                 __float2bfloat16_rn(v.y - __bfloat162float(h1)));
    lo.y = pack2(__float2bfloat16_rn(v.z - __bfloat162float(h2)),
                 __float2bfloat16_rn(v.w - __bfloat162float(h3)));
}
__device__ __forceinline__ void splitpack(float a, float b, uint32_t& hi,
                                          uint32_t& lo) {
    bf16 ha = __float2bfloat16_rn(a), hb = __float2bfloat16_rn(b);
    hi = pack2(ha, hb);
    lo = pack2(__float2bfloat16_rn(a - __bfloat162float(ha)),
               __float2bfloat16_rn(b - __bfloat162float(hb)));
}

// smem layout:
//   A stages: 2 x 18432B  (128 rows x 144B: [hi 64B][lo 64B][pad 16B])
//   B stages: 2 x 18432B  (OP0: split 144B rows; else fp32 [32 rows][132 floats])
static constexpr int AROW = 144;
static constexpr int STAGE = 128 * AROW;            // 18432
static constexpr int BBASE = 2 * STAGE;             // 36864
static constexpr int BROWF = 132 * 4;               // 528 bytes
static constexpr int DYN_SMEM = 4 * STAGE;          // 73728

// ---------------------------------------------------------------------------
// Unified 128x128-tile split-bf16 mma.sync GEMM, double-buffered pipeline.
// OP 0: scores   A=normed  B=normed (n-major) -> g_scores (scale*gate, mask)
// OP 1: attnout  A=scores(P) B=normed [k][n]  -> g_x1 = x + O
// OP 2: mlp1     A=normed2 B=W1 [k][n]        -> g_hbuf = gelu(acc + b1)
// OP 3: mlp2     A=hbuf    B=W2 [k][n]        -> out = x1 + acc + b2
// ---------------------------------------------------------------------------
template <int OP>
__global__ void __launch_bounds__(256)
gemm128(const float* __restrict__ xin, const float* __restrict__ bias,
        const float* __restrict__ stoich, const float* __restrict__ gW,
        const float* __restrict__ gb, const int* __restrict__ adj,
        const float* __restrict__ Wmat, float* __restrict__ outf) {
    extern __shared__ char smem[];
    uint32_t sb = smem_u32(smem);

    int t = threadIdx.x, wid = t >> 5, lane = t & 31;
    int mw = wid >> 2, nwp = wid & 3;   // 2 x 4 warp grid (64x32 warp tile)
    int lg = lane >> 2, lt = (lane & 3) * 4;

    int m0, n0, b = 0, h = 0, bh = 0, lda, ldb, K;
    const float *Af, *Bf;
    if (OP == 0) {
        bh = blockIdx.z; b = bh >> 3; h = bh & 7;
        m0 = blockIdx.y * 128; n0 = blockIdx.x * 128;
        lda = ldb = CD; K = CHD;
        Af = g_normed + ((size_t)b * CN + m0) * CD + h * CHD;
        Bf = g_normed + ((size_t)b * CN + n0) * CD + h * CHD;
    } else if (OP == 1) {
        bh = blockIdx.z; b = bh >> 3; h = bh & 7;
        m0 = blockIdx.y * 128; n0 = 0;
        lda = CN; ldb = CD; K = CN;
        Af = g_scores + ((size_t)bh * CN + m0) * CN;
        Bf = g_normed + (size_t)b * CN * CD + h * CHD;
    } else if (OP == 2) {
        m0 = blockIdx.y * 128; n0 = blockIdx.x * 128;
        lda = CD; ldb = CD4; K = CD;
        Af = g_normed2 + (size_t)m0 * CD;
        Bf = Wmat + n0;
    } else {
        m0 = blockIdx.y * 128; n0 = blockIdx.x * 128;
        lda = CD4; ldb = CD; K = CD4;
        Af = g_hbuf + (size_t)m0 * CD4;
        Bf = Wmat + n0;
    }
    constexpr bool BKN = (OP != 0);  // B stored [K rows][N cols] in gmem

    float acc[4][4][4];
#pragma unroll
    for (int i = 0; i < 4; i++)
#pragma unroll
        for (int j = 0; j < 4; j++)
#pragma unroll
            for (int r = 0; r < 4; r++) acc[i][j][r] = 0.f;

    const int C = K / 32;

    // A loader mapping: row = ar + 32j, float4-slot aq
    int ar = t >> 3, aq = t & 7;
    // B cp.async mapping: id = t + 256i -> row = id>>5, 16B-slot id&31
    int br = t >> 5, bq = t & 31;

    float4 rA[4], rB[4];

#define LDG_A(k0)                                                              \
    do {                                                                       \
        _Pragma("unroll") for (int j = 0; j < 4; j++)                          \
            rA[j] = *(const float4*)(Af + (size_t)(ar + 32 * j) * lda + (k0) + aq * 4); \
    } while (0)
#define LDG_B0(k0)                                                             \
    do {                                                                       \
        _Pragma("unroll") for (int j = 0; j < 4; j++)                          \
            rB[j] = *(const float4*)(Bf + (size_t)(ar + 32 * j) * ldb + (k0) + aq * 4); \
    } while (0)
#define STS_A(st)                                                              \
    do {                                                                       \
        _Pragma("unroll") for (int j = 0; j < 4; j++) {                        \
            uint2 hi, lo;                                                      \
            split4(rA[j], hi, lo);                                             \
            char* p = smem + (st) * STAGE + (ar + 32 * j) * AROW + aq * 8;     \
            *(uint2*)p = hi;                                                   \
            *(uint2*)(p + 64) = lo;                                            \
        }                                                                      \
    } while (0)
#define STS_B0(st)                                                             \
    do {                                                                       \
        _Pragma("unroll") for (int j = 0; j < 4; j++) {                        \
            uint2 hi, lo;                                                      \
            split4(rB[j], hi, lo);                                             \
            char* p = smem + BBASE + (st) * STAGE + (ar + 32 * j) * AROW + aq * 8; \
            *(uint2*)p = hi;                                                   \
            *(uint2*)(p + 64) = lo;                                            \
        }                                                                      \
    } while (0)
#define CPA_B(k0, st)                                                          \
    do {                                                                       \
        _Pragma("unroll") for (int i = 0; i < 4; i++) {                        \
            int row = br + 8 * i;                                              \
            cp16(sb + BBASE + (st) * STAGE + row * BROWF + bq * 16,            \
                 Bf + (size_t)((k0) + row) * ldb + bq * 4);                    \
        }                                                                      \
        cp_commit();                                                           \
    } while (0)

    // ---- prologue ----
    LDG_A(0);
    if (!BKN) LDG_B0(0);
    STS_A(0);
    if (!BKN) STS_B0(0);
    else CPA_B(0, 0);
    if (C > 1) {
        LDG_A(32);
        if (!BKN) LDG_B0(32);
    }
    if (BKN) cp_wait<0>();
    __syncthreads();

    for (int c = 0; c < C; c++) {
        int cur = c & 1, nxt = cur ^ 1;
        // kick next B async before compute so it lands under compute
        if (BKN && c + 1 < C) CPA_B((c + 1) * 32, nxt);

        const char* abase = smem + cur * STAGE;
        const char* bbase = smem + BBASE + cur * STAGE;
#pragma unroll
        for (int ks = 0; ks < 2; ks++) {
            uint32_t bhf[4][2], blf[4][2];
            if (!BKN) {
#pragma unroll
                for (int nf = 0; nf < 4; nf++) {
                    const char* nb =
                        bbase + (nwp * 32 + nf * 8 + lg) * AROW + ks * 32 + lt;
                    bhf[nf][0] = *(const uint32_t*)(nb);
                    bhf[nf][1] = *(const uint32_t*)(nb + 16);
                    blf[nf][0] = *(const uint32_t*)(nb + 64);
                    blf[nf][1] = *(const uint32_t*)(nb + 80);
                }
            } else {
                const float* bw = (const float*)bbase;
                int kb2 = ks * 16 + (lane & 3) * 2;
#pragma unroll
                for (int nf = 0; nf < 4; nf++) {
                    int n = nwp * 32 + nf * 8 + lg;
                    float v0 = bw[(kb2 + 0) * 132 + n];
                    float v1 = bw[(kb2 + 1) * 132 + n];
                    float v8 = bw[(kb2 + 8) * 132 + n];
                    float v9 = bw[(kb2 + 9) * 132 + n];
                    splitpack(v0, v1, bhf[nf][0], blf[nf][0]);
                    splitpack(v8, v9, bhf[nf][1], blf[nf][1]);
                }
            }
#pragma unroll
            for (int mf = 0; mf < 4; mf++) {
                const char* ma =
                    abase + (mw * 64 + mf * 16 + lg) * AROW + ks * 32 + lt;
                uint32_t ah[4], al[4];
                ah[0] = *(const uint32_t*)(ma);
                ah[1] = *(const uint32_t*)(ma + 8 * AROW);
                ah[2] = *(const uint32_t*)(ma + 16);
                ah[3] = *(const uint32_t*)(ma + 8 * AROW + 16);
                al[0] = *(const uint32_t*)(ma + 64);
                al[1] = *(const uint32_t*)(ma + 8 * AROW + 64);
                al[2] = *(const uint32_t*)(ma + 80);
                al[3] = *(const uint32_t*)(ma + 8 * AROW + 80);
#pragma unroll
                for (int nf = 0; nf < 4; nf++) {
                    mma16816(acc[mf][nf], ah, bhf[nf]);
                    mma16816(acc[mf][nf], ah, blf[nf]);
                    mma16816(acc[mf][nf], al, bhf[nf]);
                }
            }
        }

        if (c + 1 < C) {
            // store pre-fetched chunk c+1 into the other stage
            STS_A(nxt);
            if (!BKN) STS_B0(nxt);
            if (c + 2 < C) {
                LDG_A((c + 2) * 32);
                if (!BKN) LDG_B0((c + 2) * 32);
            }
            if (BKN) cp_wait<0>();
        }
        __syncthreads();
    }

    // ---- fused epilogue (c-frag: rows lg, lg+8; cols (lane&3)*2 + {0,1}) ----
    int c0 = (lane & 3) * 2;
#pragma unroll
    for (int mf = 0; mf < 4; mf++) {
#pragma unroll
        for (int half = 0; half < 2; half++) {
            int gm = m0 + mw * 64 + mf * 16 + lg + half * 8;
            if (OP == 0) {
                float sq = stoich[b * CN + gm];
                size_t srow = ((size_t)bh << 20) + (size_t)gm * CN;
                const int* arow = adj + (size_t)b * CN * CN + (size_t)gm * CN;
#pragma unroll
                for (int nf = 0; nf < 4; nf++) {
#pragma unroll
                    for (int e = 0; e < 2; e++) {
                        int gn = n0 + nwp * 32 + nf * 8 + c0 + e;
                        float v = acc[mf][nf][half * 2 + e];
                        float gate =
                            1.f / (1.f + __expf(-(sq * gW[gn] + gb[gn])));
                        g_scores[srow + gn] =
                            (arow[gn] > 0) ? v * 0.08838834764831845f * gate
                                           : -CUDART_INF_F;
                    }
                }
            } else if (OP == 1) {
                size_t base = ((size_t)b * CN + gm) * CD + h * CHD;
#pragma unroll
                for (int nf = 0; nf < 4; nf++) {
#pragma unroll
                    for (int e = 0; e < 2; e++) {
                        int gn = nwp * 32 + nf * 8 + c0 + e;
                        g_x1[base + gn] =
                            xin[base + gn] + acc[mf][nf][half * 2 + e];
                    }
                }
            } else if (OP == 2) {
                size_t base = (size_t)gm * CD4;
#pragma unroll
                for (int nf = 0; nf < 4; nf++) {
#pragma unroll
                    for (int e = 0; e < 2; e++) {
                        int gn = n0 + nwp * 32 + nf * 8 + c0 + e;
                        float u = acc[mf][nf][half * 2 + e] + bias[gn];
                        g_hbuf[base + gn] =
                            0.5f * u * (1.f + erff(u * 0.7071067811865475f));
                    }
                }
            } else {
                size_t base = (size_t)gm * CD;
#pragma unroll
                for (int nf = 0; nf < 4; nf++) {
#pragma unroll
                    for (int e = 0; e < 2; e++) {
                        int gn = n0 + nwp * 32 + nf * 8 + c0 + e;
                        outf[base + gn] = g_x1[base + gn] +
                                          acc[mf][nf][half * 2 + e] + bias[gn];
                    }
                }
            }
        }
    }
#undef LDG_A
#undef LDG_B0
#undef STS_A
#undef STS_B0
#undef CPA_B
}

// ---------------------------------------------------------------------------
// LayerNorm: sel==0: x -> g_normed ; sel==1: g_x1 -> g_normed2
// ---------------------------------------------------------------------------
__global__ void ln_kernel(const float* __restrict__ xext,
                          const float* __restrict__ lng,
                          const float* __restrict__ lnb,
                          int sel) {
    int row = blockIdx.x;
    const float* src = (sel == 0 ? xext : g_x1) + (size_t)row * CD;
    float* dst = (sel == 0 ? g_normed : g_normed2) + (size_t)row * CD;
    int t = threadIdx.x;

    float v[4];
    float s = 0.f;
#pragma unroll
    for (int i = 0; i < 4; i++) { v[i] = src[t + 256 * i]; s += v[i]; }

    __shared__ float red[8];
#pragma unroll
    for (int o = 16; o; o >>= 1) s += __shfl_xor_sync(0xffffffffu, s, o);
    if ((t & 31) == 0) red[t >> 5] = s;
    __syncthreads();
    float mean = (red[0] + red[1] + red[2] + red[3] +
                  red[4] + red[5] + red[6] + red[7]) * (1.f / CD);
    __syncthreads();

    float s2 = 0.f;
#pragma unroll
    for (int i = 0; i < 4; i++) { float d = v[i] - mean; s2 += d * d; }
#pragma unroll
    for (int o = 16; o; o >>= 1) s2 += __shfl_xor_sync(0xffffffffu, s2, o);
    if ((t & 31) == 0) red[t >> 5] = s2;
    __syncthreads();
    float var = (red[0] + red[1] + red[2] + red[3] +
                 red[4] + red[5] + red[6] + red[7]) * (1.f / CD);
    float rstd = rsqrtf(var + 1e-5f);

#pragma unroll
    for (int i = 0; i < 4; i++) {
        int c = t + 256 * i;
        dst[c] = (v[i] - mean) * rstd * lng[c] + lnb[c];
    }
}

// ---------------------------------------------------------------------------
// Row softmax over g_scores in place. grid B*H*N, 256 thr.
// ---------------------------------------------------------------------------
__global__ void softmax_kernel() {
    float* p = g_scores + (size_t)blockIdx.x * CN;
    int t = threadIdx.x;
    float v[4];
    float m = -CUDART_INF_F;
#pragma unroll
    for (int i = 0; i < 4; i++) { v[i] = p[t + 256 * i]; m = fmaxf(m, v[i]); }

    __shared__ float red[8];
#pragma unroll
    for (int o = 16; o; o >>= 1) m = fmaxf(m, __shfl_xor_sync(0xffffffffu, m, o));
    if ((t & 31) == 0) red[t >> 5] = m;
    __syncthreads();
    m = fmaxf(fmaxf(fmaxf(red[0], red[1]), fmaxf(red[2], red[3])),
              fmaxf(fmaxf(red[4], red[5]), fmaxf(red[6], red[7])));
    __syncthreads();

    float s = 0.f;
#pragma unroll
    for (int i = 0; i < 4; i++) { v[i] = __expf(v[i] - m); s += v[i]; }
#pragma unroll
    for (int o = 16; o; o >>= 1) s += __shfl_xor_sync(0xffffffffu, s, o);
    if ((t & 31) == 0) red[t >> 5] = s;
    __syncthreads();
    float tot = red[0] + red[1] + red[2] + red[3] +
                red[4] + red[5] + red[6] + red[7];
    float inv = 1.f / tot;
#pragma unroll
    for (int i = 0; i < 4; i++) p[t + 256 * i] = v[i] * inv;
}

// ---------------------------------------------------------------------------
// kernel_launch
// ---------------------------------------------------------------------------
extern "C" void kernel_launch(void* const* d_in, const int* in_sizes, int n_in,
                              void* d_out, int out_size) {
    const float* x      = (const float*)d_in[0];
    const int*   adj    = (const int*)d_in[1];
    const float* stoich = (const float*)d_in[2];
    const float* ln1_g  = (const float*)d_in[3];
    const float* ln1_b  = (const float*)d_in[4];
    const float* ln2_g  = (const float*)d_in[5];
    const float* ln2_b  = (const float*)d_in[6];
    const float* W1     = (const float*)d_in[7];
    const float* b1     = (const float*)d_in[8];
    const float* W2     = (const float*)d_in[9];
    const float* b2     = (const float*)d_in[10];
    const float* gW     = (const float*)d_in[11];
    const float* gb     = (const float*)d_in[12];
    float* out = (float*)d_out;

    // Unconditional (no static guard — harness forbids call-count state).
    // Host-side, idempotent, not a stream op; safe under graph capture.
    cudaFuncSetAttribute(gemm128<0>, cudaFuncAttributeMaxDynamicSharedMemorySize, DYN_SMEM);
    cudaFuncSetAttribute(gemm128<1>, cudaFuncAttributeMaxDynamicSharedMemorySize, DYN_SMEM);
    cudaFuncSetAttribute(gemm128<2>, cudaFuncAttributeMaxDynamicSharedMemorySize, DYN_SMEM);
    cudaFuncSetAttribute(gemm128<3>, cudaFuncAttributeMaxDynamicSharedMemorySize, DYN_SMEM);

    // LN1: x -> g_normed
    ln_kernel<<<CB * CN, 256>>>(x, ln1_g, ln1_b, 0);

    // scores = gate-masked (Q Q^T)/sqrt(HD) -> g_scores
    gemm128<0><<<dim3(8, 8, CB * CH), 256, DYN_SMEM>>>(
        nullptr, nullptr, stoich, gW, gb, adj, nullptr, nullptr);

    // softmax rows (in place)
    softmax_kernel<<<CB * CH * CN, 256>>>();

    // attention out + residual -> g_x1
    gemm128<1><<<dim3(1, 8, CB * CH), 256, DYN_SMEM>>>(
        x, nullptr, nullptr, nullptr, nullptr, nullptr, nullptr, nullptr);

    // LN2: g_x1 -> g_normed2
    ln_kernel<<<CB * CN, 256>>>(x, ln2_g, ln2_b, 1);

    // MLP1: gelu(normed2 @ W1 + b1) -> g_hbuf
    gemm128<2><<<dim3(32, 32), 256, DYN_SMEM>>>(
        nullptr, b1, nullptr, nullptr, nullptr, nullptr, W1, nullptr);

    // MLP2: out = x1 + hbuf @ W2 + b2
    gemm128<3><<<dim3(8, 32), 256, DYN_SMEM>>>(
        nullptr, b2, nullptr, nullptr, nullptr, nullptr, W2, out);
}